// round 15
// baseline (speedup 1.0000x reference)
#include <cuda_runtime.h>
#include <cuda_fp16.h>
#include <cstdint>
#include <math.h>

#define N_NODES 20000
#define N_PAD   20096            // 157 * 128
#define N_EDGES 60000
#define N_GRAPH 512
#define F_INP   7
#define HC      1024
#define NH      4
#define CH      256
#define PF      6                 // edge prefetch depth

// ---------------- scratch (static device globals; no allocation) -------------
__device__ float    g_X[(size_t)N_NODES * CH];     // final-layer output (l=3)
__device__ uint32_t g_Th[(size_t)N_PAD * 512];     // h = X@W, fp16 packed pairs
__device__ uint32_t g_Xh[(size_t)N_PAD * 512];     // next-layer GEMM input (fp16)
__device__ uint32_t g_WTh[3 * 1024 * 512];         // weight^T fp16 packed pairs
__device__ float    g_asrc[N_NODES * NH];
__device__ float    g_adst[N_NODES * NH];
__device__ float    g_aec[4 * N_EDGES * NH];       // edge attention, CSR slot order
__device__ float    g_ve[48];
__device__ float    g_ae_self[16];
__device__ float    g_eamean[3];
__device__ int      g_cnt[N_NODES];
__device__ int      g_rowptr[N_NODES + 1];
__device__ int      g_cursor[N_NODES];
__device__ int      g_eid[N_EDGES];
__device__ int      g_esrc[N_EDGES];
__device__ float    g_wedge[N_EDGES * NH];
__device__ float    g_wself[N_NODES * NH];
__device__ float    g_gate[N_NODES];
__device__ float    g_graph[N_GRAPH * CH];

__device__ __forceinline__ float lrelu(float a) { return a > 0.f ? a : 0.2f * a; }

__device__ __forceinline__ uint32_t packh2(float x, float y) {
    __half2 h = __floats2half2_rn(x, y);
    return *(uint32_t*)&h;
}
__device__ __forceinline__ float2 unpackh2(uint32_t u) {
    return __half22float2(*(__half2*)&u);
}

__device__ __forceinline__ uint32_t smem_u32(const void* p) {
    uint32_t a;
    asm("{ .reg .u64 t; cvta.to.shared.u64 t, %1; cvt.u32.u64 %0, t; }" : "=r"(a) : "l"(p));
    return a;
}
__device__ __forceinline__ void cp16(uint32_t dst, const void* src) {
    asm volatile("cp.async.cg.shared.global [%0], [%1], 16;" :: "r"(dst), "l"(src));
}
__device__ __forceinline__ void ldsm4(uint32_t* d, uint32_t addr) {
    asm volatile("ldmatrix.sync.aligned.m8n8.x4.shared.b16 {%0,%1,%2,%3}, [%4];"
                 : "=r"(d[0]), "=r"(d[1]), "=r"(d[2]), "=r"(d[3]) : "r"(addr));
}
__device__ __forceinline__ void mma_f16(float* c, uint32_t a0, uint32_t a1,
                                        uint32_t a2, uint32_t a3,
                                        uint32_t b0, uint32_t b1) {
    asm volatile(
        "mma.sync.aligned.m16n8k16.row.col.f32.f16.f16.f32 "
        "{%0,%1,%2,%3}, {%4,%5,%6,%7}, {%8,%9}, {%0,%1,%2,%3};"
        : "+f"(c[0]), "+f"(c[1]), "+f"(c[2]), "+f"(c[3])
        : "r"(a0), "r"(a1), "r"(a2), "r"(a3), "r"(b0), "r"(b1));
}

// ---------------- edge_attr mean + ve + self-loop attention (fused) ----------
__global__ void k_meanve(const float* __restrict__ ea,
                         const float* __restrict__ w_edge,
                         const float* __restrict__ att_edge) {
    __shared__ float red[3][256];
    int tid = threadIdx.x;
    float a0 = 0.f, a1 = 0.f, a2 = 0.f;
    for (int e = tid; e < N_EDGES; e += 256) {
        a0 += ea[e * 3 + 0]; a1 += ea[e * 3 + 1]; a2 += ea[e * 3 + 2];
    }
    red[0][tid] = a0; red[1][tid] = a1; red[2][tid] = a2;
    __syncthreads();
    for (int s = 128; s > 0; s >>= 1) {
        if (tid < s) {
            red[0][tid] += red[0][tid + s];
            red[1][tid] += red[1][tid + s];
            red[2][tid] += red[2][tid + s];
        }
        __syncthreads();
    }
    if (tid < 3) g_eamean[tid] = red[tid][0] * (1.f / (float)N_EDGES);
    __syncthreads();

    int warp = tid >> 5, lane = tid & 31;
    for (int idx = warp; idx < 48; idx += 8) {
        int l = idx / 12, r = idx % 12, d = r / 4, h = r % 4;
        const float* w = w_edge + (size_t)l * 3 * HC + (size_t)d * HC + h * CH;
        const float* a = att_edge + (size_t)l * HC + h * CH;
        float s = 0.f;
        for (int c = lane; c < CH; c += 32) s += w[c] * a[c];
        #pragma unroll
        for (int o = 16; o > 0; o >>= 1) s += __shfl_down_sync(0xffffffffu, s, o);
        if (lane == 0) g_ve[idx] = s;
    }
    __syncthreads();
    if (tid < 16) {
        int l = tid >> 2, h = tid & 3;
        float s = 0.f;
        for (int d = 0; d < 3; d++) s += g_eamean[d] * g_ve[l * 12 + d * 4 + h];
        g_ae_self[tid] = s;
    }
}

// edge attention written in CSR slot order
__global__ void k_ae_csr(const float* __restrict__ ea) {
    int i = blockIdx.x * blockDim.x + threadIdx.x;
    if (i >= N_EDGES) return;
    int e = g_eid[i];
    float a0 = ea[e * 3 + 0], a1 = ea[e * 3 + 1], a2 = ea[e * 3 + 2];
    #pragma unroll
    for (int l = 0; l < 4; l++) {
        float4 v;
        v.x = a0 * g_ve[l * 12 + 0] + a1 * g_ve[l * 12 + 4] + a2 * g_ve[l * 12 + 8];
        v.y = a0 * g_ve[l * 12 + 1] + a1 * g_ve[l * 12 + 5] + a2 * g_ve[l * 12 + 9];
        v.z = a0 * g_ve[l * 12 + 2] + a1 * g_ve[l * 12 + 6] + a2 * g_ve[l * 12 + 10];
        v.w = a0 * g_ve[l * 12 + 3] + a1 * g_ve[l * 12 + 7] + a2 * g_ve[l * 12 + 11];
        *(float4*)&g_aec[(size_t)l * N_EDGES * 4 + i * 4] = v;
    }
}

// ---------------- CSR build ---------------------------------------------------
__global__ void k_zero_cnt() {
    int n = blockIdx.x * blockDim.x + threadIdx.x;
    if (n < N_NODES) g_cnt[n] = 0;
}
__global__ void k_count(const int* __restrict__ ei) {
    int e = blockIdx.x * blockDim.x + threadIdx.x;
    if (e >= N_EDGES) return;
    atomicAdd(&g_cnt[ei[N_EDGES + e]], 1);
}
__global__ void k_scan() {
    __shared__ int ssum[1024];
    const int SEG = 20;
    int tid = threadIdx.x;
    int base = tid * SEG;
    int cnts[SEG];
    int tot = 0;
    #pragma unroll
    for (int j = 0; j < SEG; j++) {
        int idx = base + j;
        cnts[j] = (idx < N_NODES) ? g_cnt[idx] : 0;
        tot += cnts[j];
    }
    ssum[tid] = tot;
    __syncthreads();
    for (int off = 1; off < 1024; off <<= 1) {
        int v = (tid >= off) ? ssum[tid - off] : 0;
        __syncthreads();
        ssum[tid] += v;
        __syncthreads();
    }
    int run = ssum[tid] - tot;
    #pragma unroll
    for (int j = 0; j < SEG; j++) {
        int idx = base + j;
        if (idx < N_NODES) {
            g_rowptr[idx] = run;
            g_cursor[idx] = run;
            run += cnts[j];
        } else if (idx == N_NODES) {
            g_rowptr[N_NODES] = run;
        }
    }
}
__global__ void k_scatter(const int* __restrict__ ei) {
    int e = blockIdx.x * blockDim.x + threadIdx.x;
    if (e >= N_EDGES) return;
    int src = ei[e];
    int dst = ei[N_EDGES + e];
    int pos = atomicAdd(&g_cursor[dst], 1);
    g_eid[pos] = e;
    g_esrc[pos] = src;
}

// ------- weight transpose + fp16 pack: WT[l][n][k/2 packed] ------------------
__global__ void k_transpose(const float* __restrict__ W) {
    __shared__ float t[32][33];
    int l = blockIdx.z;
    int k0 = blockIdx.y * 32, n0 = blockIdx.x * 32;
    int tx = threadIdx.x, ty = threadIdx.y;
    const float* Wl = W + (size_t)l * 1024 * 1024;
    #pragma unroll
    for (int i = 0; i < 4; i++)
        t[ty + i * 8][tx] = Wl[(size_t)(k0 + ty + i * 8) * 1024 + n0 + tx];
    __syncthreads();
    if (tx < 16) {
        uint32_t* Wh = g_WTh + (size_t)l * 1024 * 512;
        #pragma unroll
        for (int i = 0; i < 4; i++) {
            int nl = ty + i * 8;
            int n = n0 + nl;
            Wh[(size_t)n * 512 + (k0 >> 1) + tx] = packh2(t[2 * tx][nl], t[2 * tx + 1][nl]);
        }
    }
}

// -------- layer-0 GEMM + fused alpha: Th = fp16(x @ w0); asrc/adst ------------
__global__ void k_gemm0(const float* __restrict__ x, const float* __restrict__ w0,
                        const float* __restrict__ att_src, const float* __restrict__ att_dst) {
    __shared__ float xr[F_INP];
    __shared__ float sa[8], sd[8];
    int n = blockIdx.x, tid = threadIdx.x;
    int warp = tid >> 5, lane = tid & 31;
    if (tid < F_INP) xr[tid] = x[n * F_INP + tid];
    __syncthreads();
    int c0 = tid * 4;
    float acc[4] = {0.f, 0.f, 0.f, 0.f};
    #pragma unroll
    for (int d = 0; d < F_INP; d++) {
        float xv = xr[d];
        float4 w = *(const float4*)(w0 + d * HC + c0);
        acc[0] += xv * w.x; acc[1] += xv * w.y; acc[2] += xv * w.z; acc[3] += xv * w.w;
    }
    *(uint2*)&g_Th[(size_t)n * 512 + tid * 2] =
        make_uint2(packh2(acc[0], acc[1]), packh2(acc[2], acc[3]));
    float4 a = *(const float4*)(att_src + c0);
    float4 d = *(const float4*)(att_dst + c0);
    float s1 = acc[0] * a.x + acc[1] * a.y + acc[2] * a.z + acc[3] * a.w;
    float s2 = acc[0] * d.x + acc[1] * d.y + acc[2] * d.z + acc[3] * d.w;
    #pragma unroll
    for (int o = 16; o > 0; o >>= 1) {
        s1 += __shfl_down_sync(0xffffffffu, s1, o);
        s2 += __shfl_down_sync(0xffffffffu, s2, o);
    }
    if (lane == 0) { sa[warp] = s1; sd[warp] = s2; }
    __syncthreads();
    if (tid < 4) {
        g_asrc[n * 4 + tid] = sa[2 * tid] + sa[2 * tid + 1];
        g_adst[n * 4 + tid] = sd[2 * tid] + sd[2 * tid + 1];
    }
}

// ===== mma.sync fp16 GEMM, 4-stage cp.async ring, fused alpha epilogue ========
#define NCHUNK 32
#define SROWB 80
#define OFF_A  0
#define OFF_B  10240
#define NSTAGE 4
#define STG    20480
#define GEMM_SMEM (NSTAGE * STG)       // 81920 B

__global__ void __launch_bounds__(256, 2) k_mmagemm(int layer,
                                                    const float* __restrict__ att_src,
                                                    const float* __restrict__ att_dst) {
    extern __shared__ char smem[];
    uint32_t sb = smem_u32(smem);
    int tid = threadIdx.x;
    int wid = tid >> 5;
    int lane = tid & 31;
    int g = lane >> 2, tig = lane & 3;
    int wm = wid >> 2;
    int wn = wid & 3;
    int m0 = blockIdx.y * 128;
    int n0 = blockIdx.x * 128;

    const uint32_t* Wh = g_WTh + (size_t)(layer - 1) * 1024 * 512;

    int lrow = tid & 127;
    int isB = tid >> 7;
    const uint32_t* gsrc = isB ? (Wh + (size_t)(n0 + lrow) * 512)
                               : (g_Xh + (size_t)(m0 + lrow) * 512);
    uint32_t dstrow = sb + (isB ? OFF_B : OFF_A) + lrow * SROWB;

    int q = lane >> 3, r = lane & 7;
    uint32_t aoff[4], boff[2];
    {
        int arow = (q & 1) * 8 + r;
        int acol = (q >> 1) * 16;
        #pragma unroll
        for (int mt = 0; mt < 4; mt++)
            aoff[mt] = (uint32_t)((wm * 64 + mt * 16 + arow) * SROWB + acol);
        int brow = (q >> 1) * 8 + r;
        int bcol = (q & 1) * 16;
        #pragma unroll
        for (int ntp = 0; ntp < 2; ntp++)
            boff[ntp] = (uint32_t)((wn * 32 + ntp * 16 + brow) * SROWB + bcol);
    }

    float acc[4][4][4];
    #pragma unroll
    for (int i = 0; i < 4; i++)
        #pragma unroll
        for (int j = 0; j < 4; j++)
            #pragma unroll
            for (int qq = 0; qq < 4; qq++) acc[i][j][qq] = 0.f;

    #pragma unroll
    for (int s = 0; s < NSTAGE - 1; s++) {
        uint32_t d = dstrow + s * STG;
        const uint32_t* p = gsrc + (size_t)s * 16;
        cp16(d + 0, p);
        cp16(d + 16, p + 4);
        cp16(d + 32, p + 8);
        cp16(d + 48, p + 12);
        asm volatile("cp.async.commit_group;");
    }

    for (int c = 0; c < NCHUNK; c++) {
        asm volatile("cp.async.wait_group %0;" :: "n"(NSTAGE - 2));
        __syncthreads();
        int cn = c + NSTAGE - 1;
        if (cn < NCHUNK) {
            uint32_t d = dstrow + (cn & (NSTAGE - 1)) * STG;
            const uint32_t* p = gsrc + (size_t)cn * 16;
            cp16(d + 0, p);
            cp16(d + 16, p + 4);
            cp16(d + 32, p + 8);
            cp16(d + 48, p + 12);
        }
        asm volatile("cp.async.commit_group;");

        uint32_t stq = sb + (c & (NSTAGE - 1)) * STG;
        #pragma unroll
        for (int ks = 0; ks < 2; ks++) {
            uint32_t kso = (uint32_t)(ks * 32);
            uint32_t bh[2][4];
            #pragma unroll
            for (int ntp = 0; ntp < 2; ntp++)
                ldsm4(bh[ntp], stq + OFF_B + boff[ntp] + kso);
            #pragma unroll
            for (int mt = 0; mt < 4; mt++) {
                uint32_t ah[4];
                ldsm4(ah, stq + OFF_A + aoff[mt] + kso);
                #pragma unroll
                for (int nt = 0; nt < 4; nt++) {
                    uint32_t b0 = bh[nt >> 1][(nt & 1) * 2 + 0];
                    uint32_t b1 = bh[nt >> 1][(nt & 1) * 2 + 1];
                    mma_f16(acc[mt][nt], ah[0], ah[1], ah[2], ah[3], b0, b1);
                }
            }
        }
    }

    int head = n0 >> 8;
    const float* as = att_src + (size_t)layer * HC;
    const float* ad = att_dst + (size_t)layer * HC;

    float pa[4] = {0, 0, 0, 0}, pd[4] = {0, 0, 0, 0};
    float pa8[4] = {0, 0, 0, 0}, pd8[4] = {0, 0, 0, 0};
    #pragma unroll
    for (int nt = 0; nt < 4; nt++) {
        int col = n0 + wn * 32 + nt * 8 + tig * 2;
        float2 a2 = *(const float2*)(as + col);
        float2 d2 = *(const float2*)(ad + col);
        #pragma unroll
        for (int mt = 0; mt < 4; mt++) {
            pa[mt]  += acc[mt][nt][0] * a2.x + acc[mt][nt][1] * a2.y;
            pd[mt]  += acc[mt][nt][0] * d2.x + acc[mt][nt][1] * d2.y;
            pa8[mt] += acc[mt][nt][2] * a2.x + acc[mt][nt][3] * a2.y;
            pd8[mt] += acc[mt][nt][2] * d2.x + acc[mt][nt][3] * d2.y;
        }
    }
    #pragma unroll
    for (int mt = 0; mt < 4; mt++) {
        #pragma unroll
        for (int o = 1; o <= 2; o <<= 1) {
            pa[mt]  += __shfl_xor_sync(0xffffffffu, pa[mt], o);
            pd[mt]  += __shfl_xor_sync(0xffffffffu, pd[mt], o);
            pa8[mt] += __shfl_xor_sync(0xffffffffu, pa8[mt], o);
            pd8[mt] += __shfl_xor_sync(0xffffffffu, pd8[mt], o);
        }
    }

    #pragma unroll
    for (int mt = 0; mt < 4; mt++) {
        int row0 = m0 + wm * 64 + mt * 16 + g;
        #pragma unroll
        for (int nt = 0; nt < 4; nt++) {
            int colp = (n0 + wn * 32 + nt * 8 + tig * 2) >> 1;
            if (row0 < N_NODES)
                g_Th[(size_t)row0 * 512 + colp] = packh2(acc[mt][nt][0], acc[mt][nt][1]);
            if (row0 + 8 < N_NODES)
                g_Th[(size_t)(row0 + 8) * 512 + colp] = packh2(acc[mt][nt][2], acc[mt][nt][3]);
        }
        if (tig == 0) {
            if (row0 < N_NODES) {
                atomicAdd(&g_asrc[row0 * 4 + head], pa[mt]);
                atomicAdd(&g_adst[row0 * 4 + head], pd[mt]);
            }
            if (row0 + 8 < N_NODES) {
                atomicAdd(&g_asrc[(row0 + 8) * 4 + head], pa8[mt]);
                atomicAdd(&g_adst[(row0 + 8) * 4 + head], pd8[mt]);
            }
        }
    }
}

// ---------- softmax attention weights (CSR ae, register-prefetched) -----------
__global__ void k_attw(int l) {
    int n = blockIdx.x * blockDim.x + threadIdx.x;
    if (n >= N_NODES) return;
    const float* ae = g_aec + (size_t)l * N_EDGES * 4;
    int s = g_rowptr[n], t = g_rowptr[n + 1];
    int deg = t - s;
    int dp = deg < PF ? deg : PF;

    // prefetch up to PF edges: srcs, ev (independent), then av (1 dependent hop)
    int   srcs[PF];
    float4 ev[PF], av[PF];
    #pragma unroll
    for (int j = 0; j < PF; j++) {
        if (j < dp) {
            srcs[j] = g_esrc[s + j];
            ev[j] = *(const float4*)&ae[(size_t)(s + j) * 4];
        }
    }
    #pragma unroll
    for (int j = 0; j < PF; j++)
        if (j < dp) av[j] = *(const float4*)&g_asrc[srcs[j] * 4];

    float4 ad4 = *(const float4*)&g_adst[n * 4];
    float4 as4 = *(const float4*)&g_asrc[n * 4];
    float ad[4] = {ad4.x, ad4.y, ad4.z, ad4.w};
    float aself[4], m[4];
    #pragma unroll
    for (int h = 0; h < 4; h++) {
        aself[h] = lrelu(((const float*)&as4)[h] + ad[h] + g_ae_self[l * 4 + h]);
        m[h] = aself[h];
    }
    #pragma unroll
    for (int j = 0; j < PF; j++) {
        if (j < dp) {
            #pragma unroll
            for (int h = 0; h < 4; h++) {
                float a = lrelu(((const float*)&av[j])[h] + ad[h] + ((const float*)&ev[j])[h]);
                m[h] = fmaxf(m[h], a);
            }
        }
    }
    for (int i = s + dp; i < t; i++) {
        int src = g_esrc[i];
        float4 avx = *(const float4*)&g_asrc[src * 4];
        float4 evx = *(const float4*)&ae[(size_t)i * 4];
        #pragma unroll
        for (int h = 0; h < 4; h++) {
            float a = lrelu(((const float*)&avx)[h] + ad[h] + ((const float*)&evx)[h]);
            m[h] = fmaxf(m[h], a);
        }
    }
    float sum[4];
    #pragma unroll
    for (int h = 0; h < 4; h++) sum[h] = expf(aself[h] - m[h]);
    #pragma unroll
    for (int j = 0; j < PF; j++) {
        if (j < dp) {
            #pragma unroll
            for (int h = 0; h < 4; h++) {
                float a = lrelu(((const float*)&av[j])[h] + ad[h] + ((const float*)&ev[j])[h]);
                sum[h] += expf(a - m[h]);
            }
        }
    }
    for (int i = s + dp; i < t; i++) {
        int src = g_esrc[i];
        float4 avx = *(const float4*)&g_asrc[src * 4];
        float4 evx = *(const float4*)&ae[(size_t)i * 4];
        #pragma unroll
        for (int h = 0; h < 4; h++) {
            float a = lrelu(((const float*)&avx)[h] + ad[h] + ((const float*)&evx)[h]);
            sum[h] += expf(a - m[h]);
        }
    }
    float inv[4];
    #pragma unroll
    for (int h = 0; h < 4; h++) inv[h] = 1.f / (sum[h] + 1e-16f);

    float4 ws;
    ((float*)&ws)[0] = expf(aself[0] - m[0]) * inv[0];
    ((float*)&ws)[1] = expf(aself[1] - m[1]) * inv[1];
    ((float*)&ws)[2] = expf(aself[2] - m[2]) * inv[2];
    ((float*)&ws)[3] = expf(aself[3] - m[3]) * inv[3];
    *(float4*)&g_wself[n * 4] = ws;

    #pragma unroll
    for (int j = 0; j < PF; j++) {
        if (j < dp) {
            float4 w;
            #pragma unroll
            for (int h = 0; h < 4; h++) {
                float a = lrelu(((const float*)&av[j])[h] + ad[h] + ((const float*)&ev[j])[h]);
                ((float*)&w)[h] = expf(a - m[h]) * inv[h];
            }
            *(float4*)&g_wedge[(size_t)(s + j) * 4] = w;
        }
    }
    for (int i = s + dp; i < t; i++) {
        int src = g_esrc[i];
        float4 avx = *(const float4*)&g_asrc[src * 4];
        float4 evx = *(const float4*)&ae[(size_t)i * 4];
        float4 w;
        #pragma unroll
        for (int h = 0; h < 4; h++) {
            float a = lrelu(((const float*)&avx)[h] + ad[h] + ((const float*)&evx)[h]);
            ((float*)&w)[h] = expf(a - m[h]) * inv[h];
        }
        *(float4*)&g_wedge[(size_t)i * 4] = w;
    }
}

// ------ weighted gather (prefetched) + bias (+BN+ReLU); gate on l=3 -----------
__global__ __launch_bounds__(256) void k_agg(
    int l, int concat,
    const float* __restrict__ bias012, const float* __restrict__ bias3,
    const float* __restrict__ gamma, const float* __restrict__ beta,
    const float* __restrict__ mean, const float* __restrict__ var,
    const float* __restrict__ gate_w, const float* __restrict__ gate_b) {
    __shared__ float s_red[256];
    int n = blockIdx.x;
    int tid = threadIdx.x;
    int s = g_rowptr[n], t = g_rowptr[n + 1];
    int deg = t - s;
    int dp = deg < PF ? deg : PF;

    if (concat) {
        int head = tid >> 6;
        int c4 = (tid & 63) << 2;
        int f = head * CH + c4;
        int fp = f >> 1;
        // prefetch edge meta (independent loads)
        int srcs[PF];
        float wv[PF];
        #pragma unroll
        for (int j = 0; j < PF; j++) {
            if (j < dp) {
                srcs[j] = g_esrc[s + j];
                wv[j] = g_wedge[(size_t)(s + j) * 4 + head];
            }
        }
        // issue all row gathers together
        uint2 rows[PF];
        #pragma unroll
        for (int j = 0; j < PF; j++)
            if (j < dp) rows[j] = *(const uint2*)&g_Th[(size_t)srcs[j] * 512 + fp];

        float wself = g_wself[n * 4 + head];
        uint2 hv = *(const uint2*)&g_Th[(size_t)n * 512 + fp];
        float2 v0 = unpackh2(hv.x), v1 = unpackh2(hv.y);
        float4 acc = make_float4(wself * v0.x, wself * v0.y, wself * v1.x, wself * v1.y);
        #pragma unroll
        for (int j = 0; j < PF; j++) {
            if (j < dp) {
                float2 s0 = unpackh2(rows[j].x), s1 = unpackh2(rows[j].y);
                acc.x += wv[j] * s0.x; acc.y += wv[j] * s0.y;
                acc.z += wv[j] * s1.x; acc.w += wv[j] * s1.y;
            }
        }
        for (int i = s + dp; i < t; i++) {
            int src = g_esrc[i];
            float w = g_wedge[(size_t)i * 4 + head];
            uint2 sv = *(const uint2*)&g_Th[(size_t)src * 512 + fp];
            float2 s0 = unpackh2(sv.x), s1 = unpackh2(sv.y);
            acc.x += w * s0.x; acc.y += w * s0.y; acc.z += w * s1.x; acc.w += w * s1.y;
        }
        size_t pf2 = (size_t)l * HC + f;
        float4 bv = *(const float4*)(bias012 + pf2);
        float4 gv = *(const float4*)(gamma + pf2);
        float4 be = *(const float4*)(beta + pf2);
        float4 mn = *(const float4*)(mean + pf2);
        float4 vr = *(const float4*)(var + pf2);
        float4 o;
        o.x = fmaxf((acc.x + bv.x - mn.x) * (gv.x * rsqrtf(vr.x + 1e-5f)) + be.x, 0.f);
        o.y = fmaxf((acc.y + bv.y - mn.y) * (gv.y * rsqrtf(vr.y + 1e-5f)) + be.y, 0.f);
        o.z = fmaxf((acc.z + bv.z - mn.z) * (gv.z * rsqrtf(vr.z + 1e-5f)) + be.z, 0.f);
        o.w = fmaxf((acc.w + bv.w - mn.w) * (gv.w * rsqrtf(vr.w + 1e-5f)) + be.w, 0.f);
        size_t pc = (size_t)n * 512 + fp;
        *(uint2*)&g_Xh[pc] = make_uint2(packh2(o.x, o.y), packh2(o.z, o.w));
        if (tid < 4) {
            g_asrc[n * 4 + tid] = 0.f;
            g_adst[n * 4 + tid] = 0.f;
        }
    } else {
        int c = tid;
        int ci = c >> 1, par = c & 1;
        int srcs[PF];
        float4 wv[PF];
        #pragma unroll
        for (int j = 0; j < PF; j++) {
            if (j < dp) {
                srcs[j] = g_esrc[s + j];
                wv[j] = *(const float4*)&g_wedge[(size_t)(s + j) * 4];
            }
        }
        uint4 rows0[PF];
        #pragma unroll
        for (int j = 0; j < PF; j++) {
            if (j < dp) {
                const uint32_t* hs = g_Th + (size_t)srcs[j] * 512;
                rows0[j].x = hs[ci];
                rows0[j].y = hs[128 + ci];
                rows0[j].z = hs[256 + ci];
                rows0[j].w = hs[384 + ci];
            }
        }
        float4 ws = *(const float4*)&g_wself[n * 4];
        const uint32_t* hn = g_Th + (size_t)n * 512;
        float acc;
        {
            float2 p0 = unpackh2(hn[ci]);
            float2 p1 = unpackh2(hn[128 + ci]);
            float2 p2 = unpackh2(hn[256 + ci]);
            float2 p3 = unpackh2(hn[384 + ci]);
            acc = ws.x * (par ? p0.y : p0.x) + ws.y * (par ? p1.y : p1.x)
                + ws.z * (par ? p2.y : p2.x) + ws.w * (par ? p3.y : p3.x);
        }
        #pragma unroll
        for (int j = 0; j < PF; j++) {
            if (j < dp) {
                float2 p0 = unpackh2(rows0[j].x);
                float2 p1 = unpackh2(rows0[j].y);
                float2 p2 = unpackh2(rows0[j].z);
                float2 p3 = unpackh2(rows0[j].w);
                acc += wv[j].x * (par ? p0.y : p0.x) + wv[j].y * (par ? p1.y : p1.x)
                     + wv[j].z * (par ? p2.y : p2.x) + wv[j].w * (par ? p3.y : p3.x);
            }
        }
        for (int i = s + dp; i < t; i++) {
            int src = g_esrc[i];
            float4 w = *(const float4*)&g_wedge[(size_t)i * 4];
            const uint32_t* hs = g_Th + (size_t)src * 512;
            float2 p0 = unpackh2(hs[ci]);
            float2 p1 = unpackh2(hs[128 + ci]);
            float2 p2 = unpackh2(hs[256 + ci]);
            float2 p3 = unpackh2(hs[384 + ci]);
            acc += w.x * (par ? p0.y : p0.x) + w.y * (par ? p1.y : p1.x)
                 + w.z * (par ? p2.y : p2.x) + w.w * (par ? p3.y : p3.x);
        }
        float v = 0.25f * acc + bias3[c];
        g_X[(size_t)n * CH + c] = v;
        s_red[tid] = v * gate_w[c];
        __syncthreads();
        for (int st = 128; st > 0; st >>= 1) {
            if (tid < st) s_red[tid] += s_red[tid + st];
            __syncthreads();
        }
        if (tid == 0) g_gate[n] = s_red[0] + gate_b[0];
    }
}

// ---------------- per-graph softmax pooling -----------------------------------
__device__ __forceinline__ int lb_batch(const int* __restrict__ batch, int target) {
    int lo = 0, hi = N_NODES;
    while (lo < hi) {
        int mid = (lo + hi) >> 1;
        if (batch[mid] < target) lo = mid + 1; else hi = mid;
    }
    return lo;
}
__global__ void k_pool(const int* __restrict__ batch) {
    int b = blockIdx.x;
    int c = threadIdx.x;
    int s = lb_batch(batch, b);
    int e = lb_batch(batch, b + 1);
    if (s == e) { g_graph[b * CH + c] = 0.f; return; }
    float mx = -1e30f;
    for (int n = s; n < e; n++) mx = fmaxf(mx, g_gate[n]);
    float sum = 0.f;
    for (int n = s; n < e; n++) sum += expf(g_gate[n] - mx);
    float inv = 1.f / (sum + 1e-16f);
    float acc = 0.f;
    for (int n = s; n < e; n++)
        acc += expf(g_gate[n] - mx) * inv * g_X[(size_t)n * CH + c];
    g_graph[b * CH + c] = acc;
}

// ---------------- final projection --------------------------------------------
__global__ __launch_bounds__(256) void k_proj(const float* __restrict__ proj_w,
                                              const float* __restrict__ proj_b,
                                              float* __restrict__ out) {
    __shared__ float sg[8][CH];
    int b0 = blockIdx.x * 8;
    int tid = threadIdx.x;
    #pragma unroll
    for (int g = 0; g < 8; g++) sg[g][tid] = g_graph[(b0 + g) * CH + tid];
    __syncthreads();
    float acc[8][4];
    #pragma unroll
    for (int g = 0; g < 8; g++)
        #pragma unroll
        for (int j = 0; j < 4; j++) acc[g][j] = 0.f;
    for (int cIt = 0; cIt < CH; cIt++) {
        float w0 = proj_w[cIt * 1024 + tid];
        float w1 = proj_w[cIt * 1024 + tid + 256];
        float w2 = proj_w[cIt * 1024 + tid + 512];
        float w3 = proj_w[cIt * 1024 + tid + 768];
        #pragma unroll
        for (int g = 0; g < 8; g++) {
            float sv = sg[g][cIt];
            acc[g][0] += sv * w0;
            acc[g][1] += sv * w1;
            acc[g][2] += sv * w2;
            acc[g][3] += sv * w3;
        }
    }
    #pragma unroll
    for (int g = 0; g < 8; g++)
        #pragma unroll
        for (int j = 0; j < 4; j++)
            out[(size_t)(b0 + g) * 1024 + tid + j * 256] = acc[g][j] + proj_b[tid + j * 256];
}

// ---------------- host orchestration ------------------------------------------
extern "C" void kernel_launch(void* const* d_in, const int* in_sizes, int n_in,
                              void* d_out, int out_size) {
    (void)in_sizes; (void)n_in; (void)out_size;
    const float* x        = (const float*)d_in[0];
    const int*   ei       = (const int*)d_in[1];
    const float* ea       = (const float*)d_in[2];
    const int*   batch    = (const int*)d_in[3];
    const float* w0       = (const float*)d_in[4];
    const float* w_rest   = (const float*)d_in[5];
    const float* w_edge   = (const float*)d_in[6];
    const float* att_src  = (const float*)d_in[7];
    const float* att_dst  = (const float*)d_in[8];
    const float* att_edge = (const float*)d_in[9];
    const float* bias012  = (const float*)d_in[10];
    const float* bias3    = (const float*)d_in[11];
    const float* bn_gamma = (const float*)d_in[12];
    const float* bn_beta  = (const float*)d_in[13];
    const float* bn_mean  = (const float*)d_in[14];
    const float* bn_var   = (const float*)d_in[15];
    const float* gate_w   = (const float*)d_in[16];
    const float* gate_b   = (const float*)d_in[17];
    const float* proj_w   = (const float*)d_in[18];
    const float* proj_b   = (const float*)d_in[19];
    float* out = (float*)d_out;

    cudaFuncSetAttribute(k_mmagemm, cudaFuncAttributeMaxDynamicSharedMemorySize, GEMM_SMEM);

    k_zero_cnt<<<(N_NODES + 255) / 256, 256>>>();
    k_count<<<(N_EDGES + 255) / 256, 256>>>(ei);
    k_scan<<<1, 1024>>>();
    k_scatter<<<(N_EDGES + 255) / 256, 256>>>(ei);
    k_transpose<<<dim3(32, 32, 3), dim3(32, 8)>>>(w_rest);
    k_gemm0<<<N_NODES, 256>>>(x, w0, att_src, att_dst);
    k_meanve<<<1, 256>>>(ea, w_edge, att_edge);
    k_ae_csr<<<(N_EDGES + 127) / 128, 128>>>(ea);

    for (int l = 0; l < 4; l++) {
        if (l > 0) {
            k_mmagemm<<<dim3(8, (N_NODES + 127) / 128), 256, GEMM_SMEM>>>(l, att_src, att_dst);
        }
        k_attw<<<(N_NODES + 255) / 256, 256>>>(l);
        k_agg<<<N_NODES, 256>>>(l, l < 3 ? 1 : 0, bias012, bias3,
                                bn_gamma, bn_beta, bn_mean, bn_var, gate_w, gate_b);
    }

    k_pool<<<N_GRAPH, 256>>>(batch);
    k_proj<<<N_GRAPH / 8, 256>>>(proj_w, proj_b, out);
}

// round 16
// speedup vs baseline: 1.6651x; 1.6651x over previous
#include <cuda_runtime.h>
#include <cuda_fp16.h>
#include <cstdint>
#include <math.h>

#define N_NODES 20000
#define N_PAD   20096            // 157 * 128
#define N_EDGES 60000
#define N_GRAPH 512
#define F_INP   7
#define HC      1024
#define NH      4
#define CH      256

// ---------------- scratch (static device globals; no allocation) -------------
__device__ float    g_X[(size_t)N_NODES * CH];     // final-layer output (l=3)
__device__ uint32_t g_Th[(size_t)N_PAD * 512];     // h = X@W, fp16 packed pairs
__device__ uint32_t g_Xh[(size_t)N_PAD * 512];     // next-layer GEMM input (fp16)
__device__ uint32_t g_WTh[3 * 1024 * 512];         // weight^T fp16 packed pairs
__device__ float    g_asrc[N_NODES * NH];
__device__ float    g_adst[N_NODES * NH];
__device__ float    g_aec[4 * N_EDGES * NH];       // edge attention, CSR slot order
__device__ float    g_ve[48];
__device__ float    g_ae_self[16];
__device__ float    g_eamean[3];
__device__ int      g_cnt[N_NODES];
__device__ int      g_rowptr[N_NODES + 1];
__device__ int      g_cursor[N_NODES];
__device__ int      g_eid[N_EDGES];
__device__ int      g_esrc[N_EDGES];
__device__ float    g_wedge[N_EDGES * NH];
__device__ float    g_wself[N_NODES * NH];
__device__ float    g_gate[N_NODES];
__device__ float    g_graph[N_GRAPH * CH];

__device__ __forceinline__ float lrelu(float a) { return a > 0.f ? a : 0.2f * a; }

__device__ __forceinline__ uint32_t packh2(float x, float y) {
    __half2 h = __floats2half2_rn(x, y);
    return *(uint32_t*)&h;
}
__device__ __forceinline__ float2 unpackh2(uint32_t u) {
    return __half22float2(*(__half2*)&u);
}

__device__ __forceinline__ uint32_t smem_u32(const void* p) {
    uint32_t a;
    asm("{ .reg .u64 t; cvta.to.shared.u64 t, %1; cvt.u32.u64 %0, t; }" : "=r"(a) : "l"(p));
    return a;
}
__device__ __forceinline__ void cp16(uint32_t dst, const void* src) {
    asm volatile("cp.async.cg.shared.global [%0], [%1], 16;" :: "r"(dst), "l"(src));
}
__device__ __forceinline__ void ldsm4(uint32_t* d, uint32_t addr) {
    asm volatile("ldmatrix.sync.aligned.m8n8.x4.shared.b16 {%0,%1,%2,%3}, [%4];"
                 : "=r"(d[0]), "=r"(d[1]), "=r"(d[2]), "=r"(d[3]) : "r"(addr));
}
__device__ __forceinline__ void mma_f16(float* c, uint32_t a0, uint32_t a1,
                                        uint32_t a2, uint32_t a3,
                                        uint32_t b0, uint32_t b1) {
    asm volatile(
        "mma.sync.aligned.m16n8k16.row.col.f32.f16.f16.f32 "
        "{%0,%1,%2,%3}, {%4,%5,%6,%7}, {%8,%9}, {%0,%1,%2,%3};"
        : "+f"(c[0]), "+f"(c[1]), "+f"(c[2]), "+f"(c[3])
        : "r"(a0), "r"(a1), "r"(a2), "r"(a3), "r"(b0), "r"(b1));
}

// ---------------- edge_attr mean + ve + self-loop attention (fused) ----------
__global__ void k_meanve(const float* __restrict__ ea,
                         const float* __restrict__ w_edge,
                         const float* __restrict__ att_edge) {
    __shared__ float red[3][256];
    int tid = threadIdx.x;
    float a0 = 0.f, a1 = 0.f, a2 = 0.f;
    for (int e = tid; e < N_EDGES; e += 256) {
        a0 += ea[e * 3 + 0]; a1 += ea[e * 3 + 1]; a2 += ea[e * 3 + 2];
    }
    red[0][tid] = a0; red[1][tid] = a1; red[2][tid] = a2;
    __syncthreads();
    for (int s = 128; s > 0; s >>= 1) {
        if (tid < s) {
            red[0][tid] += red[0][tid + s];
            red[1][tid] += red[1][tid + s];
            red[2][tid] += red[2][tid + s];
        }
        __syncthreads();
    }
    if (tid < 3) g_eamean[tid] = red[tid][0] * (1.f / (float)N_EDGES);
    __syncthreads();

    int warp = tid >> 5, lane = tid & 31;
    for (int idx = warp; idx < 48; idx += 8) {
        int l = idx / 12, r = idx % 12, d = r / 4, h = r % 4;
        const float* w = w_edge + (size_t)l * 3 * HC + (size_t)d * HC + h * CH;
        const float* a = att_edge + (size_t)l * HC + h * CH;
        float s = 0.f;
        for (int c = lane; c < CH; c += 32) s += w[c] * a[c];
        #pragma unroll
        for (int o = 16; o > 0; o >>= 1) s += __shfl_down_sync(0xffffffffu, s, o);
        if (lane == 0) g_ve[idx] = s;
    }
    __syncthreads();
    if (tid < 16) {
        int l = tid >> 2, h = tid & 3;
        float s = 0.f;
        for (int d = 0; d < 3; d++) s += g_eamean[d] * g_ve[l * 12 + d * 4 + h];
        g_ae_self[tid] = s;
    }
}

// edge attention written in CSR slot order
__global__ void k_ae_csr(const float* __restrict__ ea) {
    int i = blockIdx.x * blockDim.x + threadIdx.x;
    if (i >= N_EDGES) return;
    int e = g_eid[i];
    float a0 = ea[e * 3 + 0], a1 = ea[e * 3 + 1], a2 = ea[e * 3 + 2];
    #pragma unroll
    for (int l = 0; l < 4; l++) {
        float4 v;
        v.x = a0 * g_ve[l * 12 + 0] + a1 * g_ve[l * 12 + 4] + a2 * g_ve[l * 12 + 8];
        v.y = a0 * g_ve[l * 12 + 1] + a1 * g_ve[l * 12 + 5] + a2 * g_ve[l * 12 + 9];
        v.z = a0 * g_ve[l * 12 + 2] + a1 * g_ve[l * 12 + 6] + a2 * g_ve[l * 12 + 10];
        v.w = a0 * g_ve[l * 12 + 3] + a1 * g_ve[l * 12 + 7] + a2 * g_ve[l * 12 + 11];
        *(float4*)&g_aec[(size_t)l * N_EDGES * 4 + i * 4] = v;
    }
}

// ---------------- CSR build ---------------------------------------------------
__global__ void k_zero_cnt() {
    int n = blockIdx.x * blockDim.x + threadIdx.x;
    if (n < N_NODES) g_cnt[n] = 0;
}
__global__ void k_count(const int* __restrict__ ei) {
    int e = blockIdx.x * blockDim.x + threadIdx.x;
    if (e >= N_EDGES) return;
    atomicAdd(&g_cnt[ei[N_EDGES + e]], 1);
}
__global__ void k_scan() {
    __shared__ int ssum[1024];
    const int SEG = 20;
    int tid = threadIdx.x;
    int base = tid * SEG;
    int cnts[SEG];
    int tot = 0;
    #pragma unroll
    for (int j = 0; j < SEG; j++) {
        int idx = base + j;
        cnts[j] = (idx < N_NODES) ? g_cnt[idx] : 0;
        tot += cnts[j];
    }
    ssum[tid] = tot;
    __syncthreads();
    for (int off = 1; off < 1024; off <<= 1) {
        int v = (tid >= off) ? ssum[tid - off] : 0;
        __syncthreads();
        ssum[tid] += v;
        __syncthreads();
    }
    int run = ssum[tid] - tot;
    #pragma unroll
    for (int j = 0; j < SEG; j++) {
        int idx = base + j;
        if (idx < N_NODES) {
            g_rowptr[idx] = run;
            g_cursor[idx] = run;
            run += cnts[j];
        } else if (idx == N_NODES) {
            g_rowptr[N_NODES] = run;
        }
    }
}
__global__ void k_scatter(const int* __restrict__ ei) {
    int e = blockIdx.x * blockDim.x + threadIdx.x;
    if (e >= N_EDGES) return;
    int src = ei[e];
    int dst = ei[N_EDGES + e];
    int pos = atomicAdd(&g_cursor[dst], 1);
    g_eid[pos] = e;
    g_esrc[pos] = src;
}

// ------- weight transpose + fp16 pack: WT[l][n][k/2 packed] ------------------
__global__ void k_transpose(const float* __restrict__ W) {
    __shared__ float t[32][33];
    int l = blockIdx.z;
    int k0 = blockIdx.y * 32, n0 = blockIdx.x * 32;
    int tx = threadIdx.x, ty = threadIdx.y;
    const float* Wl = W + (size_t)l * 1024 * 1024;
    #pragma unroll
    for (int i = 0; i < 4; i++)
        t[ty + i * 8][tx] = Wl[(size_t)(k0 + ty + i * 8) * 1024 + n0 + tx];
    __syncthreads();
    if (tx < 16) {
        uint32_t* Wh = g_WTh + (size_t)l * 1024 * 512;
        #pragma unroll
        for (int i = 0; i < 4; i++) {
            int nl = ty + i * 8;
            int n = n0 + nl;
            Wh[(size_t)n * 512 + (k0 >> 1) + tx] = packh2(t[2 * tx][nl], t[2 * tx + 1][nl]);
        }
    }
}

// -------- layer-0 GEMM + fused alpha: Th = fp16(x @ w0); asrc/adst ------------
__global__ void k_gemm0(const float* __restrict__ x, const float* __restrict__ w0,
                        const float* __restrict__ att_src, const float* __restrict__ att_dst) {
    __shared__ float xr[F_INP];
    __shared__ float sa[8], sd[8];
    int n = blockIdx.x, tid = threadIdx.x;
    int warp = tid >> 5, lane = tid & 31;
    if (tid < F_INP) xr[tid] = x[n * F_INP + tid];
    __syncthreads();
    int c0 = tid * 4;
    float acc[4] = {0.f, 0.f, 0.f, 0.f};
    #pragma unroll
    for (int d = 0; d < F_INP; d++) {
        float xv = xr[d];
        float4 w = *(const float4*)(w0 + d * HC + c0);
        acc[0] += xv * w.x; acc[1] += xv * w.y; acc[2] += xv * w.z; acc[3] += xv * w.w;
    }
    *(uint2*)&g_Th[(size_t)n * 512 + tid * 2] =
        make_uint2(packh2(acc[0], acc[1]), packh2(acc[2], acc[3]));
    float4 a = *(const float4*)(att_src + c0);
    float4 d = *(const float4*)(att_dst + c0);
    float s1 = acc[0] * a.x + acc[1] * a.y + acc[2] * a.z + acc[3] * a.w;
    float s2 = acc[0] * d.x + acc[1] * d.y + acc[2] * d.z + acc[3] * d.w;
    #pragma unroll
    for (int o = 16; o > 0; o >>= 1) {
        s1 += __shfl_down_sync(0xffffffffu, s1, o);
        s2 += __shfl_down_sync(0xffffffffu, s2, o);
    }
    if (lane == 0) { sa[warp] = s1; sd[warp] = s2; }
    __syncthreads();
    if (tid < 4) {
        g_asrc[n * 4 + tid] = sa[2 * tid] + sa[2 * tid + 1];
        g_adst[n * 4 + tid] = sd[2 * tid] + sd[2 * tid + 1];
    }
}

// ===== mma.sync fp16 GEMM, 4-stage cp.async ring, fused alpha epilogue ========
#define NCHUNK 32
#define SROWB 80
#define OFF_A  0
#define OFF_B  10240
#define NSTAGE 4
#define STG    20480
#define GEMM_SMEM (NSTAGE * STG)       // 81920 B

__global__ void __launch_bounds__(256, 2) k_mmagemm(int layer,
                                                    const float* __restrict__ att_src,
                                                    const float* __restrict__ att_dst) {
    extern __shared__ char smem[];
    uint32_t sb = smem_u32(smem);
    int tid = threadIdx.x;
    int wid = tid >> 5;
    int lane = tid & 31;
    int g = lane >> 2, tig = lane & 3;
    int wm = wid >> 2;
    int wn = wid & 3;
    int m0 = blockIdx.y * 128;
    int n0 = blockIdx.x * 128;

    const uint32_t* Wh = g_WTh + (size_t)(layer - 1) * 1024 * 512;

    int lrow = tid & 127;
    int isB = tid >> 7;
    const uint32_t* gsrc = isB ? (Wh + (size_t)(n0 + lrow) * 512)
                               : (g_Xh + (size_t)(m0 + lrow) * 512);
    uint32_t dstrow = sb + (isB ? OFF_B : OFF_A) + lrow * SROWB;

    int q = lane >> 3, r = lane & 7;
    uint32_t aoff[4], boff[2];
    {
        int arow = (q & 1) * 8 + r;
        int acol = (q >> 1) * 16;
        #pragma unroll
        for (int mt = 0; mt < 4; mt++)
            aoff[mt] = (uint32_t)((wm * 64 + mt * 16 + arow) * SROWB + acol);
        int brow = (q >> 1) * 8 + r;
        int bcol = (q & 1) * 16;
        #pragma unroll
        for (int ntp = 0; ntp < 2; ntp++)
            boff[ntp] = (uint32_t)((wn * 32 + ntp * 16 + brow) * SROWB + bcol);
    }

    float acc[4][4][4];
    #pragma unroll
    for (int i = 0; i < 4; i++)
        #pragma unroll
        for (int j = 0; j < 4; j++)
            #pragma unroll
            for (int qq = 0; qq < 4; qq++) acc[i][j][qq] = 0.f;

    #pragma unroll
    for (int s = 0; s < NSTAGE - 1; s++) {
        uint32_t d = dstrow + s * STG;
        const uint32_t* p = gsrc + (size_t)s * 16;
        cp16(d + 0, p);
        cp16(d + 16, p + 4);
        cp16(d + 32, p + 8);
        cp16(d + 48, p + 12);
        asm volatile("cp.async.commit_group;");
    }

    for (int c = 0; c < NCHUNK; c++) {
        asm volatile("cp.async.wait_group %0;" :: "n"(NSTAGE - 2));
        __syncthreads();
        int cn = c + NSTAGE - 1;
        if (cn < NCHUNK) {
            uint32_t d = dstrow + (cn & (NSTAGE - 1)) * STG;
            const uint32_t* p = gsrc + (size_t)cn * 16;
            cp16(d + 0, p);
            cp16(d + 16, p + 4);
            cp16(d + 32, p + 8);
            cp16(d + 48, p + 12);
        }
        asm volatile("cp.async.commit_group;");

        uint32_t stq = sb + (c & (NSTAGE - 1)) * STG;
        #pragma unroll
        for (int ks = 0; ks < 2; ks++) {
            uint32_t kso = (uint32_t)(ks * 32);
            uint32_t bh[2][4];
            #pragma unroll
            for (int ntp = 0; ntp < 2; ntp++)
                ldsm4(bh[ntp], stq + OFF_B + boff[ntp] + kso);
            #pragma unroll
            for (int mt = 0; mt < 4; mt++) {
                uint32_t ah[4];
                ldsm4(ah, stq + OFF_A + aoff[mt] + kso);
                #pragma unroll
                for (int nt = 0; nt < 4; nt++) {
                    uint32_t b0 = bh[nt >> 1][(nt & 1) * 2 + 0];
                    uint32_t b1 = bh[nt >> 1][(nt & 1) * 2 + 1];
                    mma_f16(acc[mt][nt], ah[0], ah[1], ah[2], ah[3], b0, b1);
                }
            }
        }
    }

    int head = n0 >> 8;
    const float* as = att_src + (size_t)layer * HC;
    const float* ad = att_dst + (size_t)layer * HC;

    float pa[4] = {0, 0, 0, 0}, pd[4] = {0, 0, 0, 0};
    float pa8[4] = {0, 0, 0, 0}, pd8[4] = {0, 0, 0, 0};
    #pragma unroll
    for (int nt = 0; nt < 4; nt++) {
        int col = n0 + wn * 32 + nt * 8 + tig * 2;
        float2 a2 = *(const float2*)(as + col);
        float2 d2 = *(const float2*)(ad + col);
        #pragma unroll
        for (int mt = 0; mt < 4; mt++) {
            pa[mt]  += acc[mt][nt][0] * a2.x + acc[mt][nt][1] * a2.y;
            pd[mt]  += acc[mt][nt][0] * d2.x + acc[mt][nt][1] * d2.y;
            pa8[mt] += acc[mt][nt][2] * a2.x + acc[mt][nt][3] * a2.y;
            pd8[mt] += acc[mt][nt][2] * d2.x + acc[mt][nt][3] * d2.y;
        }
    }
    #pragma unroll
    for (int mt = 0; mt < 4; mt++) {
        #pragma unroll
        for (int o = 1; o <= 2; o <<= 1) {
            pa[mt]  += __shfl_xor_sync(0xffffffffu, pa[mt], o);
            pd[mt]  += __shfl_xor_sync(0xffffffffu, pd[mt], o);
            pa8[mt] += __shfl_xor_sync(0xffffffffu, pa8[mt], o);
            pd8[mt] += __shfl_xor_sync(0xffffffffu, pd8[mt], o);
        }
    }

    #pragma unroll
    for (int mt = 0; mt < 4; mt++) {
        int row0 = m0 + wm * 64 + mt * 16 + g;
        #pragma unroll
        for (int nt = 0; nt < 4; nt++) {
            int colp = (n0 + wn * 32 + nt * 8 + tig * 2) >> 1;
            if (row0 < N_NODES)
                g_Th[(size_t)row0 * 512 + colp] = packh2(acc[mt][nt][0], acc[mt][nt][1]);
            if (row0 + 8 < N_NODES)
                g_Th[(size_t)(row0 + 8) * 512 + colp] = packh2(acc[mt][nt][2], acc[mt][nt][3]);
        }
        if (tig == 0) {
            if (row0 < N_NODES) {
                atomicAdd(&g_asrc[row0 * 4 + head], pa[mt]);
                atomicAdd(&g_adst[row0 * 4 + head], pd[mt]);
            }
            if (row0 + 8 < N_NODES) {
                atomicAdd(&g_asrc[(row0 + 8) * 4 + head], pa8[mt]);
                atomicAdd(&g_adst[(row0 + 8) * 4 + head], pd8[mt]);
            }
        }
    }
}

// ---------------- precompute softmax attention weights (CSR-ordered ae) -------
__global__ void k_attw(int l) {
    int n = blockIdx.x * blockDim.x + threadIdx.x;
    if (n >= N_NODES) return;
    const float* ae = g_aec + (size_t)l * N_EDGES * 4;
    int s = g_rowptr[n], t = g_rowptr[n + 1];

    float4 ad4 = *(const float4*)&g_adst[n * 4];
    float4 as4 = *(const float4*)&g_asrc[n * 4];
    float ad[4] = {ad4.x, ad4.y, ad4.z, ad4.w};
    float aself[4], m[4];
    #pragma unroll
    for (int h = 0; h < 4; h++) {
        aself[h] = lrelu(((const float*)&as4)[h] + ad[h] + g_ae_self[l * 4 + h]);
        m[h] = aself[h];
    }
    for (int i = s; i < t; i++) {
        int src = g_esrc[i];
        float4 av = *(const float4*)&g_asrc[src * 4];
        float4 ev = *(const float4*)&ae[i * 4];
        #pragma unroll
        for (int h = 0; h < 4; h++) {
            float a = lrelu(((const float*)&av)[h] + ad[h] + ((const float*)&ev)[h]);
            m[h] = fmaxf(m[h], a);
        }
    }
    float sum[4];
    #pragma unroll
    for (int h = 0; h < 4; h++) sum[h] = expf(aself[h] - m[h]);
    for (int i = s; i < t; i++) {
        int src = g_esrc[i];
        float4 av = *(const float4*)&g_asrc[src * 4];
        float4 ev = *(const float4*)&ae[i * 4];
        #pragma unroll
        for (int h = 0; h < 4; h++) {
            float a = lrelu(((const float*)&av)[h] + ad[h] + ((const float*)&ev)[h]);
            sum[h] += expf(a - m[h]);
        }
    }
    float inv[4];
    #pragma unroll
    for (int h = 0; h < 4; h++) inv[h] = 1.f / (sum[h] + 1e-16f);

    float4 ws;
    ((float*)&ws)[0] = expf(aself[0] - m[0]) * inv[0];
    ((float*)&ws)[1] = expf(aself[1] - m[1]) * inv[1];
    ((float*)&ws)[2] = expf(aself[2] - m[2]) * inv[2];
    ((float*)&ws)[3] = expf(aself[3] - m[3]) * inv[3];
    *(float4*)&g_wself[n * 4] = ws;

    for (int i = s; i < t; i++) {
        int src = g_esrc[i];
        float4 av = *(const float4*)&g_asrc[src * 4];
        float4 ev = *(const float4*)&ae[i * 4];
        float4 w;
        #pragma unroll
        for (int h = 0; h < 4; h++) {
            float a = lrelu(((const float*)&av)[h] + ad[h] + ((const float*)&ev)[h]);
            ((float*)&w)[h] = expf(a - m[h]) * inv[h];
        }
        *(float4*)&g_wedge[i * 4] = w;
    }
}

// ------ weighted gather + bias (+BN+ReLU); zeroes alpha; fused gate on l=3 ----
__global__ __launch_bounds__(256) void k_agg(
    int l, int concat,
    const float* __restrict__ bias012, const float* __restrict__ bias3,
    const float* __restrict__ gamma, const float* __restrict__ beta,
    const float* __restrict__ mean, const float* __restrict__ var,
    const float* __restrict__ gate_w, const float* __restrict__ gate_b) {
    __shared__ float s_red[256];
    int n = blockIdx.x;
    int tid = threadIdx.x;
    int s = g_rowptr[n], t = g_rowptr[n + 1];

    if (concat) {
        int head = tid >> 6;
        int c4 = (tid & 63) << 2;
        int f = head * CH + c4;
        int fp = f >> 1;
        float wself = g_wself[n * 4 + head];
        uint2 hv = *(const uint2*)&g_Th[(size_t)n * 512 + fp];
        float2 v0 = unpackh2(hv.x), v1 = unpackh2(hv.y);
        float4 acc = make_float4(wself * v0.x, wself * v0.y, wself * v1.x, wself * v1.y);
        for (int i = s; i < t; i++) {
            int src = g_esrc[i];
            float w = g_wedge[i * 4 + head];
            uint2 sv = *(const uint2*)&g_Th[(size_t)src * 512 + fp];
            float2 s0 = unpackh2(sv.x), s1 = unpackh2(sv.y);
            acc.x += w * s0.x; acc.y += w * s0.y; acc.z += w * s1.x; acc.w += w * s1.y;
        }
        size_t pf = (size_t)l * HC + f;
        float4 bv = *(const float4*)(bias012 + pf);
        float4 gv = *(const float4*)(gamma + pf);
        float4 be = *(const float4*)(beta + pf);
        float4 mn = *(const float4*)(mean + pf);
        float4 vr = *(const float4*)(var + pf);
        float4 o;
        o.x = fmaxf((acc.x + bv.x - mn.x) * (gv.x * rsqrtf(vr.x + 1e-5f)) + be.x, 0.f);
        o.y = fmaxf((acc.y + bv.y - mn.y) * (gv.y * rsqrtf(vr.y + 1e-5f)) + be.y, 0.f);
        o.z = fmaxf((acc.z + bv.z - mn.z) * (gv.z * rsqrtf(vr.z + 1e-5f)) + be.z, 0.f);
        o.w = fmaxf((acc.w + bv.w - mn.w) * (gv.w * rsqrtf(vr.w + 1e-5f)) + be.w, 0.f);
        size_t pc = (size_t)n * 512 + fp;
        *(uint2*)&g_Xh[pc] = make_uint2(packh2(o.x, o.y), packh2(o.z, o.w));
        if (tid < 4) {
            g_asrc[n * 4 + tid] = 0.f;
            g_adst[n * 4 + tid] = 0.f;
        }
    } else {
        int c = tid;
        float4 ws = *(const float4*)&g_wself[n * 4];
        const uint32_t* hn = g_Th + (size_t)n * 512;
        int ci = c >> 1, par = c & 1;
        float acc;
        {
            float2 p0 = unpackh2(hn[ci]);
            float2 p1 = unpackh2(hn[128 + ci]);
            float2 p2 = unpackh2(hn[256 + ci]);
            float2 p3 = unpackh2(hn[384 + ci]);
            acc = ws.x * (par ? p0.y : p0.x) + ws.y * (par ? p1.y : p1.x)
                + ws.z * (par ? p2.y : p2.x) + ws.w * (par ? p3.y : p3.x);
        }
        for (int i = s; i < t; i++) {
            int src = g_esrc[i];
            float4 w = *(const float4*)&g_wedge[i * 4];
            const uint32_t* hs = g_Th + (size_t)src * 512;
            float2 p0 = unpackh2(hs[ci]);
            float2 p1 = unpackh2(hs[128 + ci]);
            float2 p2 = unpackh2(hs[256 + ci]);
            float2 p3 = unpackh2(hs[384 + ci]);
            acc += w.x * (par ? p0.y : p0.x) + w.y * (par ? p1.y : p1.x)
                 + w.z * (par ? p2.y : p2.x) + w.w * (par ? p3.y : p3.x);
        }
        float v = 0.25f * acc + bias3[c];
        g_X[(size_t)n * CH + c] = v;
        s_red[tid] = v * gate_w[c];
        __syncthreads();
        for (int st = 128; st > 0; st >>= 1) {
            if (tid < st) s_red[tid] += s_red[tid + st];
            __syncthreads();
        }
        if (tid == 0) g_gate[n] = s_red[0] + gate_b[0];
    }
}

// ---------------- per-graph softmax pooling -----------------------------------
__device__ __forceinline__ int lb_batch(const int* __restrict__ batch, int target) {
    int lo = 0, hi = N_NODES;
    while (lo < hi) {
        int mid = (lo + hi) >> 1;
        if (batch[mid] < target) lo = mid + 1; else hi = mid;
    }
    return lo;
}
__global__ void k_pool(const int* __restrict__ batch) {
    int b = blockIdx.x;
    int c = threadIdx.x;
    int s = lb_batch(batch, b);
    int e = lb_batch(batch, b + 1);
    if (s == e) { g_graph[b * CH + c] = 0.f; return; }
    float mx = -1e30f;
    for (int n = s; n < e; n++) mx = fmaxf(mx, g_gate[n]);
    float sum = 0.f;
    for (int n = s; n < e; n++) sum += expf(g_gate[n] - mx);
    float inv = 1.f / (sum + 1e-16f);
    float acc = 0.f;
    for (int n = s; n < e; n++)
        acc += expf(g_gate[n] - mx) * inv * g_X[(size_t)n * CH + c];
    g_graph[b * CH + c] = acc;
}

// ---------------- final projection --------------------------------------------
__global__ __launch_bounds__(256) void k_proj(const float* __restrict__ proj_w,
                                              const float* __restrict__ proj_b,
                                              float* __restrict__ out) {
    __shared__ float sg[8][CH];
    int b0 = blockIdx.x * 8;
    int tid = threadIdx.x;
    #pragma unroll
    for (int g = 0; g < 8; g++) sg[g][tid] = g_graph[(b0 + g) * CH + tid];
    __syncthreads();
    float acc[8][4];
    #pragma unroll
    for (int g = 0; g < 8; g++)
        #pragma unroll
        for (int j = 0; j < 4; j++) acc[g][j] = 0.f;
    for (int cIt = 0; cIt < CH; cIt++) {
        float w0 = proj_w[cIt * 1024 + tid];
        float w1 = proj_w[cIt * 1024 + tid + 256];
        float w2 = proj_w[cIt * 1024 + tid + 512];
        float w3 = proj_w[cIt * 1024 + tid + 768];
        #pragma unroll
        for (int g = 0; g < 8; g++) {
            float sv = sg[g][cIt];
            acc[g][0] += sv * w0;
            acc[g][1] += sv * w1;
            acc[g][2] += sv * w2;
            acc[g][3] += sv * w3;
        }
    }
    #pragma unroll
    for (int g = 0; g < 8; g++)
        #pragma unroll
        for (int j = 0; j < 4; j++)
            out[(size_t)(b0 + g) * 1024 + tid + j * 256] = acc[g][j] + proj_b[tid + j * 256];
}

// ---------------- host orchestration ------------------------------------------
extern "C" void kernel_launch(void* const* d_in, const int* in_sizes, int n_in,
                              void* d_out, int out_size) {
    (void)in_sizes; (void)n_in; (void)out_size;
    const float* x        = (const float*)d_in[0];
    const int*   ei       = (const int*)d_in[1];
    const float* ea       = (const float*)d_in[2];
    const int*   batch    = (const int*)d_in[3];
    const float* w0       = (const float*)d_in[4];
    const float* w_rest   = (const float*)d_in[5];
    const float* w_edge   = (const float*)d_in[6];
    const float* att_src  = (const float*)d_in[7];
    const float* att_dst  = (const float*)d_in[8];
    const float* att_edge = (const float*)d_in[9];
    const float* bias012  = (const float*)d_in[10];
    const float* bias3    = (const float*)d_in[11];
    const float* bn_gamma = (const float*)d_in[12];
    const float* bn_beta  = (const float*)d_in[13];
    const float* bn_mean  = (const float*)d_in[14];
    const float* bn_var   = (const float*)d_in[15];
    const float* gate_w   = (const float*)d_in[16];
    const float* gate_b   = (const float*)d_in[17];
    const float* proj_w   = (const float*)d_in[18];
    const float* proj_b   = (const float*)d_in[19];
    float* out = (float*)d_out;

    cudaFuncSetAttribute(k_mmagemm, cudaFuncAttributeMaxDynamicSharedMemorySize, GEMM_SMEM);

    k_zero_cnt<<<(N_NODES + 255) / 256, 256>>>();
    k_count<<<(N_EDGES + 255) / 256, 256>>>(ei);
    k_scan<<<1, 1024>>>();
    k_scatter<<<(N_EDGES + 255) / 256, 256>>>(ei);
    k_transpose<<<dim3(32, 32, 3), dim3(32, 8)>>>(w_rest);
    k_gemm0<<<N_NODES, 256>>>(x, w0, att_src, att_dst);
    k_meanve<<<1, 256>>>(ea, w_edge, att_edge);
    k_ae_csr<<<(N_EDGES + 127) / 128, 128>>>(ea);

    for (int l = 0; l < 4; l++) {
        if (l > 0) {
            k_mmagemm<<<dim3(8, (N_NODES + 127) / 128), 256, GEMM_SMEM>>>(l, att_src, att_dst);
        }
        k_attw<<<(N_NODES + 63) / 64, 64>>>(l);   // 313 CTAs -> all SMs busy
        k_agg<<<N_NODES, 256>>>(l, l < 3 ? 1 : 0, bias012, bias3,
                                bn_gamma, bn_beta, bn_mean, bn_var, gate_w, gate_b);
    }

    k_pool<<<N_GRAPH, 256>>>(batch);
    k_proj<<<N_GRAPH / 8, 256>>>(proj_w, proj_b, out);
}

// round 17
// speedup vs baseline: 1.6920x; 1.0161x over previous
#include <cuda_runtime.h>
#include <cuda_fp16.h>
#include <cstdint>
#include <math.h>

#define N_NODES 20000
#define N_PAD   20096            // 157 * 128
#define N_EDGES 60000
#define N_GRAPH 512
#define F_INP   7
#define HC      1024
#define NH      4
#define CH      256

// ---------------- scratch (static device globals; no allocation) -------------
__device__ float    g_X[(size_t)N_NODES * CH];     // final-layer output (l=3)
__device__ uint32_t g_Th[(size_t)N_PAD * 512];     // h = X@W, fp16 packed pairs
__device__ uint32_t g_Xh[(size_t)N_PAD * 512];     // next-layer GEMM input (fp16)
__device__ uint32_t g_WTh[3 * 1024 * 512];         // weight^T fp16 packed pairs
__device__ float    g_asrc[N_NODES * NH];
__device__ float    g_adst[N_NODES * NH];
__device__ float    g_aec[4 * N_EDGES * NH];       // edge attention, CSR slot order
__device__ float    g_ve[48];
__device__ float    g_ae_self[16];
__device__ float    g_eamean[3];
__device__ int      g_cnt[N_NODES];
__device__ int      g_rowptr[N_NODES + 1];
__device__ int      g_cursor[N_NODES];
__device__ int      g_eid[N_EDGES];
__device__ int      g_esrc[N_EDGES];
__device__ float    g_wedge[N_EDGES * NH];
__device__ float    g_wself[N_NODES * NH];
__device__ float    g_gate[N_NODES];
__device__ float    g_graph[N_GRAPH * CH];

__device__ __forceinline__ float lrelu(float a) { return a > 0.f ? a : 0.2f * a; }

__device__ __forceinline__ uint32_t packh2(float x, float y) {
    __half2 h = __floats2half2_rn(x, y);
    return *(uint32_t*)&h;
}
__device__ __forceinline__ float2 unpackh2(uint32_t u) {
    return __half22float2(*(__half2*)&u);
}

__device__ __forceinline__ uint32_t smem_u32(const void* p) {
    uint32_t a;
    asm("{ .reg .u64 t; cvta.to.shared.u64 t, %1; cvt.u32.u64 %0, t; }" : "=r"(a) : "l"(p));
    return a;
}
__device__ __forceinline__ void cp16(uint32_t dst, const void* src) {
    asm volatile("cp.async.cg.shared.global [%0], [%1], 16;" :: "r"(dst), "l"(src));
}
__device__ __forceinline__ void ldsm4(uint32_t* d, uint32_t addr) {
    asm volatile("ldmatrix.sync.aligned.m8n8.x4.shared.b16 {%0,%1,%2,%3}, [%4];"
                 : "=r"(d[0]), "=r"(d[1]), "=r"(d[2]), "=r"(d[3]) : "r"(addr));
}
__device__ __forceinline__ void mma_f16(float* c, uint32_t a0, uint32_t a1,
                                        uint32_t a2, uint32_t a3,
                                        uint32_t b0, uint32_t b1) {
    asm volatile(
        "mma.sync.aligned.m16n8k16.row.col.f32.f16.f16.f32 "
        "{%0,%1,%2,%3}, {%4,%5,%6,%7}, {%8,%9}, {%0,%1,%2,%3};"
        : "+f"(c[0]), "+f"(c[1]), "+f"(c[2]), "+f"(c[3])
        : "r"(a0), "r"(a1), "r"(a2), "r"(a3), "r"(b0), "r"(b1));
}

// ---------------- edge_attr mean + ve + self-loop attention (fused) ----------
__global__ void k_meanve(const float* __restrict__ ea,
                         const float* __restrict__ w_edge,
                         const float* __restrict__ att_edge) {
    __shared__ float red[3][256];
    int tid = threadIdx.x;
    float a0 = 0.f, a1 = 0.f, a2 = 0.f;
    for (int e = tid; e < N_EDGES; e += 256) {
        a0 += ea[e * 3 + 0]; a1 += ea[e * 3 + 1]; a2 += ea[e * 3 + 2];
    }
    red[0][tid] = a0; red[1][tid] = a1; red[2][tid] = a2;
    __syncthreads();
    for (int s = 128; s > 0; s >>= 1) {
        if (tid < s) {
            red[0][tid] += red[0][tid + s];
            red[1][tid] += red[1][tid + s];
            red[2][tid] += red[2][tid + s];
        }
        __syncthreads();
    }
    if (tid < 3) g_eamean[tid] = red[tid][0] * (1.f / (float)N_EDGES);
    __syncthreads();

    int warp = tid >> 5, lane = tid & 31;
    for (int idx = warp; idx < 48; idx += 8) {
        int l = idx / 12, r = idx % 12, d = r / 4, h = r % 4;
        const float* w = w_edge + (size_t)l * 3 * HC + (size_t)d * HC + h * CH;
        const float* a = att_edge + (size_t)l * HC + h * CH;
        float s = 0.f;
        for (int c = lane; c < CH; c += 32) s += w[c] * a[c];
        #pragma unroll
        for (int o = 16; o > 0; o >>= 1) s += __shfl_down_sync(0xffffffffu, s, o);
        if (lane == 0) g_ve[idx] = s;
    }
    __syncthreads();
    if (tid < 16) {
        int l = tid >> 2, h = tid & 3;
        float s = 0.f;
        for (int d = 0; d < 3; d++) s += g_eamean[d] * g_ve[l * 12 + d * 4 + h];
        g_ae_self[tid] = s;
    }
}

// edge attention written in CSR slot order
__global__ void k_ae_csr(const float* __restrict__ ea) {
    int i = blockIdx.x * blockDim.x + threadIdx.x;
    if (i >= N_EDGES) return;
    int e = g_eid[i];
    float a0 = ea[e * 3 + 0], a1 = ea[e * 3 + 1], a2 = ea[e * 3 + 2];
    #pragma unroll
    for (int l = 0; l < 4; l++) {
        float4 v;
        v.x = a0 * g_ve[l * 12 + 0] + a1 * g_ve[l * 12 + 4] + a2 * g_ve[l * 12 + 8];
        v.y = a0 * g_ve[l * 12 + 1] + a1 * g_ve[l * 12 + 5] + a2 * g_ve[l * 12 + 9];
        v.z = a0 * g_ve[l * 12 + 2] + a1 * g_ve[l * 12 + 6] + a2 * g_ve[l * 12 + 10];
        v.w = a0 * g_ve[l * 12 + 3] + a1 * g_ve[l * 12 + 7] + a2 * g_ve[l * 12 + 11];
        *(float4*)&g_aec[(size_t)l * N_EDGES * 4 + i * 4] = v;
    }
}

// ---------------- CSR build ---------------------------------------------------
__global__ void k_zero_cnt() {
    int n = blockIdx.x * blockDim.x + threadIdx.x;
    if (n < N_NODES) g_cnt[n] = 0;
}
__global__ void k_count(const int* __restrict__ ei) {
    int e = blockIdx.x * blockDim.x + threadIdx.x;
    if (e >= N_EDGES) return;
    atomicAdd(&g_cnt[ei[N_EDGES + e]], 1);
}
__global__ void k_scan() {
    __shared__ int ssum[1024];
    const int SEG = 20;
    int tid = threadIdx.x;
    int base = tid * SEG;
    int cnts[SEG];
    int tot = 0;
    #pragma unroll
    for (int j = 0; j < SEG; j++) {
        int idx = base + j;
        cnts[j] = (idx < N_NODES) ? g_cnt[idx] : 0;
        tot += cnts[j];
    }
    ssum[tid] = tot;
    __syncthreads();
    for (int off = 1; off < 1024; off <<= 1) {
        int v = (tid >= off) ? ssum[tid - off] : 0;
        __syncthreads();
        ssum[tid] += v;
        __syncthreads();
    }
    int run = ssum[tid] - tot;
    #pragma unroll
    for (int j = 0; j < SEG; j++) {
        int idx = base + j;
        if (idx < N_NODES) {
            g_rowptr[idx] = run;
            g_cursor[idx] = run;
            run += cnts[j];
        } else if (idx == N_NODES) {
            g_rowptr[N_NODES] = run;
        }
    }
}
__global__ void k_scatter(const int* __restrict__ ei) {
    int e = blockIdx.x * blockDim.x + threadIdx.x;
    if (e >= N_EDGES) return;
    int src = ei[e];
    int dst = ei[N_EDGES + e];
    int pos = atomicAdd(&g_cursor[dst], 1);
    g_eid[pos] = e;
    g_esrc[pos] = src;
}

// ------- weight transpose + fp16 pack: WT[l][n][k/2 packed] ------------------
__global__ void k_transpose(const float* __restrict__ W) {
    __shared__ float t[32][33];
    int l = blockIdx.z;
    int k0 = blockIdx.y * 32, n0 = blockIdx.x * 32;
    int tx = threadIdx.x, ty = threadIdx.y;
    const float* Wl = W + (size_t)l * 1024 * 1024;
    #pragma unroll
    for (int i = 0; i < 4; i++)
        t[ty + i * 8][tx] = Wl[(size_t)(k0 + ty + i * 8) * 1024 + n0 + tx];
    __syncthreads();
    if (tx < 16) {
        uint32_t* Wh = g_WTh + (size_t)l * 1024 * 512;
        #pragma unroll
        for (int i = 0; i < 4; i++) {
            int nl = ty + i * 8;
            int n = n0 + nl;
            Wh[(size_t)n * 512 + (k0 >> 1) + tx] = packh2(t[2 * tx][nl], t[2 * tx + 1][nl]);
        }
    }
}

// -------- layer-0 GEMM + fused alpha: Th = fp16(x @ w0); asrc/adst ------------
__global__ void k_gemm0(const float* __restrict__ x, const float* __restrict__ w0,
                        const float* __restrict__ att_src, const float* __restrict__ att_dst) {
    __shared__ float xr[F_INP];
    __shared__ float sa[8], sd[8];
    int n = blockIdx.x, tid = threadIdx.x;
    int warp = tid >> 5, lane = tid & 31;
    if (tid < F_INP) xr[tid] = x[n * F_INP + tid];
    __syncthreads();
    int c0 = tid * 4;
    float acc[4] = {0.f, 0.f, 0.f, 0.f};
    #pragma unroll
    for (int d = 0; d < F_INP; d++) {
        float xv = xr[d];
        float4 w = *(const float4*)(w0 + d * HC + c0);
        acc[0] += xv * w.x; acc[1] += xv * w.y; acc[2] += xv * w.z; acc[3] += xv * w.w;
    }
    *(uint2*)&g_Th[(size_t)n * 512 + tid * 2] =
        make_uint2(packh2(acc[0], acc[1]), packh2(acc[2], acc[3]));
    float4 a = *(const float4*)(att_src + c0);
    float4 d = *(const float4*)(att_dst + c0);
    float s1 = acc[0] * a.x + acc[1] * a.y + acc[2] * a.z + acc[3] * a.w;
    float s2 = acc[0] * d.x + acc[1] * d.y + acc[2] * d.z + acc[3] * d.w;
    #pragma unroll
    for (int o = 16; o > 0; o >>= 1) {
        s1 += __shfl_down_sync(0xffffffffu, s1, o);
        s2 += __shfl_down_sync(0xffffffffu, s2, o);
    }
    if (lane == 0) { sa[warp] = s1; sd[warp] = s2; }
    __syncthreads();
    if (tid < 4) {
        g_asrc[n * 4 + tid] = sa[2 * tid] + sa[2 * tid + 1];
        g_adst[n * 4 + tid] = sd[2 * tid] + sd[2 * tid + 1];
    }
}

// ===== mma.sync fp16 GEMM, 4-stage cp.async ring, fused alpha epilogue ========
#define NCHUNK 32
#define SROWB 80
#define OFF_A  0
#define OFF_B  10240
#define NSTAGE 4
#define STG    20480
#define GEMM_SMEM (NSTAGE * STG)       // 81920 B

__global__ void __launch_bounds__(256, 2) k_mmagemm(int layer,
                                                    const float* __restrict__ att_src,
                                                    const float* __restrict__ att_dst) {
    extern __shared__ char smem[];
    uint32_t sb = smem_u32(smem);
    int tid = threadIdx.x;
    int wid = tid >> 5;
    int lane = tid & 31;
    int g = lane >> 2, tig = lane & 3;
    int wm = wid >> 2;
    int wn = wid & 3;
    int m0 = blockIdx.y * 128;
    int n0 = blockIdx.x * 128;

    const uint32_t* Wh = g_WTh + (size_t)(layer - 1) * 1024 * 512;

    int lrow = tid & 127;
    int isB = tid >> 7;
    const uint32_t* gsrc = isB ? (Wh + (size_t)(n0 + lrow) * 512)
                               : (g_Xh + (size_t)(m0 + lrow) * 512);
    uint32_t dstrow = sb + (isB ? OFF_B : OFF_A) + lrow * SROWB;

    int q = lane >> 3, r = lane & 7;
    uint32_t aoff[4], boff[2];
    {
        int arow = (q & 1) * 8 + r;
        int acol = (q >> 1) * 16;
        #pragma unroll
        for (int mt = 0; mt < 4; mt++)
            aoff[mt] = (uint32_t)((wm * 64 + mt * 16 + arow) * SROWB + acol);
        int brow = (q >> 1) * 8 + r;
        int bcol = (q & 1) * 16;
        #pragma unroll
        for (int ntp = 0; ntp < 2; ntp++)
            boff[ntp] = (uint32_t)((wn * 32 + ntp * 16 + brow) * SROWB + bcol);
    }

    float acc[4][4][4];
    #pragma unroll
    for (int i = 0; i < 4; i++)
        #pragma unroll
        for (int j = 0; j < 4; j++)
            #pragma unroll
            for (int qq = 0; qq < 4; qq++) acc[i][j][qq] = 0.f;

    #pragma unroll
    for (int s = 0; s < NSTAGE - 1; s++) {
        uint32_t d = dstrow + s * STG;
        const uint32_t* p = gsrc + (size_t)s * 16;
        cp16(d + 0, p);
        cp16(d + 16, p + 4);
        cp16(d + 32, p + 8);
        cp16(d + 48, p + 12);
        asm volatile("cp.async.commit_group;");
    }

    for (int c = 0; c < NCHUNK; c++) {
        asm volatile("cp.async.wait_group %0;" :: "n"(NSTAGE - 2));
        __syncthreads();
        int cn = c + NSTAGE - 1;
        if (cn < NCHUNK) {
            uint32_t d = dstrow + (cn & (NSTAGE - 1)) * STG;
            const uint32_t* p = gsrc + (size_t)cn * 16;
            cp16(d + 0, p);
            cp16(d + 16, p + 4);
            cp16(d + 32, p + 8);
            cp16(d + 48, p + 12);
        }
        asm volatile("cp.async.commit_group;");

        uint32_t stq = sb + (c & (NSTAGE - 1)) * STG;
        #pragma unroll
        for (int ks = 0; ks < 2; ks++) {
            uint32_t kso = (uint32_t)(ks * 32);
            uint32_t bh[2][4];
            #pragma unroll
            for (int ntp = 0; ntp < 2; ntp++)
                ldsm4(bh[ntp], stq + OFF_B + boff[ntp] + kso);
            #pragma unroll
            for (int mt = 0; mt < 4; mt++) {
                uint32_t ah[4];
                ldsm4(ah, stq + OFF_A + aoff[mt] + kso);
                #pragma unroll
                for (int nt = 0; nt < 4; nt++) {
                    uint32_t b0 = bh[nt >> 1][(nt & 1) * 2 + 0];
                    uint32_t b1 = bh[nt >> 1][(nt & 1) * 2 + 1];
                    mma_f16(acc[mt][nt], ah[0], ah[1], ah[2], ah[3], b0, b1);
                }
            }
        }
    }

    int head = n0 >> 8;
    const float* as = att_src + (size_t)layer * HC;
    const float* ad = att_dst + (size_t)layer * HC;

    float pa[4] = {0, 0, 0, 0}, pd[4] = {0, 0, 0, 0};
    float pa8[4] = {0, 0, 0, 0}, pd8[4] = {0, 0, 0, 0};
    #pragma unroll
    for (int nt = 0; nt < 4; nt++) {
        int col = n0 + wn * 32 + nt * 8 + tig * 2;
        float2 a2 = *(const float2*)(as + col);
        float2 d2 = *(const float2*)(ad + col);
        #pragma unroll
        for (int mt = 0; mt < 4; mt++) {
            pa[mt]  += acc[mt][nt][0] * a2.x + acc[mt][nt][1] * a2.y;
            pd[mt]  += acc[mt][nt][0] * d2.x + acc[mt][nt][1] * d2.y;
            pa8[mt] += acc[mt][nt][2] * a2.x + acc[mt][nt][3] * a2.y;
            pd8[mt] += acc[mt][nt][2] * d2.x + acc[mt][nt][3] * d2.y;
        }
    }
    #pragma unroll
    for (int mt = 0; mt < 4; mt++) {
        #pragma unroll
        for (int o = 1; o <= 2; o <<= 1) {
            pa[mt]  += __shfl_xor_sync(0xffffffffu, pa[mt], o);
            pd[mt]  += __shfl_xor_sync(0xffffffffu, pd[mt], o);
            pa8[mt] += __shfl_xor_sync(0xffffffffu, pa8[mt], o);
            pd8[mt] += __shfl_xor_sync(0xffffffffu, pd8[mt], o);
        }
    }

    #pragma unroll
    for (int mt = 0; mt < 4; mt++) {
        int row0 = m0 + wm * 64 + mt * 16 + g;
        #pragma unroll
        for (int nt = 0; nt < 4; nt++) {
            int colp = (n0 + wn * 32 + nt * 8 + tig * 2) >> 1;
            if (row0 < N_NODES)
                g_Th[(size_t)row0 * 512 + colp] = packh2(acc[mt][nt][0], acc[mt][nt][1]);
            if (row0 + 8 < N_NODES)
                g_Th[(size_t)(row0 + 8) * 512 + colp] = packh2(acc[mt][nt][2], acc[mt][nt][3]);
        }
        if (tig == 0) {
            if (row0 < N_NODES) {
                atomicAdd(&g_asrc[row0 * 4 + head], pa[mt]);
                atomicAdd(&g_adst[row0 * 4 + head], pd[mt]);
            }
            if (row0 + 8 < N_NODES) {
                atomicAdd(&g_asrc[(row0 + 8) * 4 + head], pa8[mt]);
                atomicAdd(&g_adst[(row0 + 8) * 4 + head], pd8[mt]);
            }
        }
    }
}

// ---------------- precompute softmax attention weights (CSR-ordered ae) -------
__global__ void k_attw(int l) {
    int n = blockIdx.x * blockDim.x + threadIdx.x;
    if (n >= N_NODES) return;
    const float* ae = g_aec + (size_t)l * N_EDGES * 4;
    int s = g_rowptr[n], t = g_rowptr[n + 1];

    float4 ad4 = *(const float4*)&g_adst[n * 4];
    float4 as4 = *(const float4*)&g_asrc[n * 4];
    float ad[4] = {ad4.x, ad4.y, ad4.z, ad4.w};
    float aself[4], m[4];
    #pragma unroll
    for (int h = 0; h < 4; h++) {
        aself[h] = lrelu(((const float*)&as4)[h] + ad[h] + g_ae_self[l * 4 + h]);
        m[h] = aself[h];
    }
    for (int i = s; i < t; i++) {
        int src = g_esrc[i];
        float4 av = *(const float4*)&g_asrc[src * 4];
        float4 ev = *(const float4*)&ae[i * 4];
        #pragma unroll
        for (int h = 0; h < 4; h++) {
            float a = lrelu(((const float*)&av)[h] + ad[h] + ((const float*)&ev)[h]);
            m[h] = fmaxf(m[h], a);
        }
    }
    float sum[4];
    #pragma unroll
    for (int h = 0; h < 4; h++) sum[h] = expf(aself[h] - m[h]);
    for (int i = s; i < t; i++) {
        int src = g_esrc[i];
        float4 av = *(const float4*)&g_asrc[src * 4];
        float4 ev = *(const float4*)&ae[i * 4];
        #pragma unroll
        for (int h = 0; h < 4; h++) {
            float a = lrelu(((const float*)&av)[h] + ad[h] + ((const float*)&ev)[h]);
            sum[h] += expf(a - m[h]);
        }
    }
    float inv[4];
    #pragma unroll
    for (int h = 0; h < 4; h++) inv[h] = 1.f / (sum[h] + 1e-16f);

    float4 ws;
    ((float*)&ws)[0] = expf(aself[0] - m[0]) * inv[0];
    ((float*)&ws)[1] = expf(aself[1] - m[1]) * inv[1];
    ((float*)&ws)[2] = expf(aself[2] - m[2]) * inv[2];
    ((float*)&ws)[3] = expf(aself[3] - m[3]) * inv[3];
    *(float4*)&g_wself[n * 4] = ws;

    for (int i = s; i < t; i++) {
        int src = g_esrc[i];
        float4 av = *(const float4*)&g_asrc[src * 4];
        float4 ev = *(const float4*)&ae[i * 4];
        float4 w;
        #pragma unroll
        for (int h = 0; h < 4; h++) {
            float a = lrelu(((const float*)&av)[h] + ad[h] + ((const float*)&ev)[h]);
            ((float*)&w)[h] = expf(a - m[h]) * inv[h];
        }
        *(float4*)&g_wedge[i * 4] = w;
    }
}

// ------ weighted gather + bias (+BN+ReLU); 128 thr/node, uint4 gathers --------
__global__ __launch_bounds__(128) void k_agg(
    int l, int concat,
    const float* __restrict__ bias012, const float* __restrict__ bias3,
    const float* __restrict__ gamma, const float* __restrict__ beta,
    const float* __restrict__ mean, const float* __restrict__ var,
    const float* __restrict__ gate_w, const float* __restrict__ gate_b) {
    __shared__ float s_red[128];
    int n = blockIdx.x;
    int tid = threadIdx.x;
    int s = g_rowptr[n], t = g_rowptr[n + 1];

    if (concat) {
        int head = tid >> 5;                 // 0..3
        int c8 = (tid & 31) << 3;            // 0..248
        int f = head * CH + c8;
        int fp = f >> 1;                     // uint32 index; 4 consecutive
        float wself = g_wself[n * 4 + head];
        uint4 hv = *(const uint4*)&g_Th[(size_t)n * 512 + fp];
        float2 v0 = unpackh2(hv.x), v1 = unpackh2(hv.y), v2 = unpackh2(hv.z), v3 = unpackh2(hv.w);
        float acc[8] = {wself * v0.x, wself * v0.y, wself * v1.x, wself * v1.y,
                        wself * v2.x, wself * v2.y, wself * v3.x, wself * v3.y};
        for (int i = s; i < t; i++) {
            int src = g_esrc[i];
            float w = g_wedge[i * 4 + head];
            uint4 sv = *(const uint4*)&g_Th[(size_t)src * 512 + fp];
            float2 q0 = unpackh2(sv.x), q1 = unpackh2(sv.y), q2 = unpackh2(sv.z), q3 = unpackh2(sv.w);
            acc[0] += w * q0.x; acc[1] += w * q0.y; acc[2] += w * q1.x; acc[3] += w * q1.y;
            acc[4] += w * q2.x; acc[5] += w * q2.y; acc[6] += w * q3.x; acc[7] += w * q3.y;
        }
        size_t pf = (size_t)l * HC + f;
        uint4 outp;
        uint32_t* op = (uint32_t*)&outp;
        #pragma unroll
        for (int half = 0; half < 2; half++) {
            float4 bv = *(const float4*)(bias012 + pf + half * 4);
            float4 gv = *(const float4*)(gamma + pf + half * 4);
            float4 be = *(const float4*)(beta + pf + half * 4);
            float4 mn = *(const float4*)(mean + pf + half * 4);
            float4 vr = *(const float4*)(var + pf + half * 4);
            float o0 = fmaxf((acc[half * 4 + 0] + bv.x - mn.x) * (gv.x * rsqrtf(vr.x + 1e-5f)) + be.x, 0.f);
            float o1 = fmaxf((acc[half * 4 + 1] + bv.y - mn.y) * (gv.y * rsqrtf(vr.y + 1e-5f)) + be.y, 0.f);
            float o2 = fmaxf((acc[half * 4 + 2] + bv.z - mn.z) * (gv.z * rsqrtf(vr.z + 1e-5f)) + be.z, 0.f);
            float o3 = fmaxf((acc[half * 4 + 3] + bv.w - mn.w) * (gv.w * rsqrtf(vr.w + 1e-5f)) + be.w, 0.f);
            op[half * 2 + 0] = packh2(o0, o1);
            op[half * 2 + 1] = packh2(o2, o3);
        }
        *(uint4*)&g_Xh[(size_t)n * 512 + fp] = outp;
        if (tid < 4) {
            g_asrc[n * 4 + tid] = 0.f;
            g_adst[n * 4 + tid] = 0.f;
        }
    } else {
        int ci = tid;                        // uint32 index: channels 2ci, 2ci+1
        float4 ws = *(const float4*)&g_wself[n * 4];
        const uint32_t* hn = g_Th + (size_t)n * 512;
        float a0, a1;
        {
            float2 p0 = unpackh2(hn[ci]);
            float2 p1 = unpackh2(hn[128 + ci]);
            float2 p2 = unpackh2(hn[256 + ci]);
            float2 p3 = unpackh2(hn[384 + ci]);
            a0 = ws.x * p0.x + ws.y * p1.x + ws.z * p2.x + ws.w * p3.x;
            a1 = ws.x * p0.y + ws.y * p1.y + ws.z * p2.y + ws.w * p3.y;
        }
        for (int i = s; i < t; i++) {
            int src = g_esrc[i];
            float4 w = *(const float4*)&g_wedge[i * 4];
            const uint32_t* hs = g_Th + (size_t)src * 512;
            float2 p0 = unpackh2(hs[ci]);
            float2 p1 = unpackh2(hs[128 + ci]);
            float2 p2 = unpackh2(hs[256 + ci]);
            float2 p3 = unpackh2(hs[384 + ci]);
            a0 += w.x * p0.x + w.y * p1.x + w.z * p2.x + w.w * p3.x;
            a1 += w.x * p0.y + w.y * p1.y + w.z * p2.y + w.w * p3.y;
        }
        float2 b2 = *(const float2*)(bias3 + 2 * ci);
        float v0 = 0.25f * a0 + b2.x;
        float v1 = 0.25f * a1 + b2.y;
        *(float2*)&g_X[(size_t)n * CH + 2 * ci] = make_float2(v0, v1);
        float2 gw = *(const float2*)(gate_w + 2 * ci);
        s_red[tid] = v0 * gw.x + v1 * gw.y;
        __syncthreads();
        for (int st = 64; st > 0; st >>= 1) {
            if (tid < st) s_red[tid] += s_red[tid + st];
            __syncthreads();
        }
        if (tid == 0) g_gate[n] = s_red[0] + gate_b[0];
    }
}

// ---------------- per-graph softmax pooling -----------------------------------
__device__ __forceinline__ int lb_batch(const int* __restrict__ batch, int target) {
    int lo = 0, hi = N_NODES;
    while (lo < hi) {
        int mid = (lo + hi) >> 1;
        if (batch[mid] < target) lo = mid + 1; else hi = mid;
    }
    return lo;
}
__global__ void k_pool(const int* __restrict__ batch) {
    int b = blockIdx.x;
    int c = threadIdx.x;
    int s = lb_batch(batch, b);
    int e = lb_batch(batch, b + 1);
    if (s == e) { g_graph[b * CH + c] = 0.f; return; }
    float mx = -1e30f;
    for (int n = s; n < e; n++) mx = fmaxf(mx, g_gate[n]);
    float sum = 0.f;
    for (int n = s; n < e; n++) sum += expf(g_gate[n] - mx);
    float inv = 1.f / (sum + 1e-16f);
    float acc = 0.f;
    for (int n = s; n < e; n++)
        acc += expf(g_gate[n] - mx) * inv * g_X[(size_t)n * CH + c];
    g_graph[b * CH + c] = acc;
}

// ---------------- final projection --------------------------------------------
__global__ __launch_bounds__(256) void k_proj(const float* __restrict__ proj_w,
                                              const float* __restrict__ proj_b,
                                              float* __restrict__ out) {
    __shared__ float sg[8][CH];
    int b0 = blockIdx.x * 8;
    int tid = threadIdx.x;
    #pragma unroll
    for (int g = 0; g < 8; g++) sg[g][tid] = g_graph[(b0 + g) * CH + tid];
    __syncthreads();
    float acc[8][4];
    #pragma unroll
    for (int g = 0; g < 8; g++)
        #pragma unroll
        for (int j = 0; j < 4; j++) acc[g][j] = 0.f;
    for (int cIt = 0; cIt < CH; cIt++) {
        float w0 = proj_w[cIt * 1024 + tid];
        float w1 = proj_w[cIt * 1024 + tid + 256];
        float w2 = proj_w[cIt * 1024 + tid + 512];
        float w3 = proj_w[cIt * 1024 + tid + 768];
        #pragma unroll
        for (int g = 0; g < 8; g++) {
            float sv = sg[g][cIt];
            acc[g][0] += sv * w0;
            acc[g][1] += sv * w1;
            acc[g][2] += sv * w2;
            acc[g][3] += sv * w3;
        }
    }
    #pragma unroll
    for (int g = 0; g < 8; g++)
        #pragma unroll
        for (int j = 0; j < 4; j++)
            out[(size_t)(b0 + g) * 1024 + tid + j * 256] = acc[g][j] + proj_b[tid + j * 256];
}

// ---------------- host orchestration ------------------------------------------
extern "C" void kernel_launch(void* const* d_in, const int* in_sizes, int n_in,
                              void* d_out, int out_size) {
    (void)in_sizes; (void)n_in; (void)out_size;
    const float* x        = (const float*)d_in[0];
    const int*   ei       = (const int*)d_in[1];
    const float* ea       = (const float*)d_in[2];
    const int*   batch    = (const int*)d_in[3];
    const float* w0       = (const float*)d_in[4];
    const float* w_rest   = (const float*)d_in[5];
    const float* w_edge   = (const float*)d_in[6];
    const float* att_src  = (const float*)d_in[7];
    const float* att_dst  = (const float*)d_in[8];
    const float* att_edge = (const float*)d_in[9];
    const float* bias012  = (const float*)d_in[10];
    const float* bias3    = (const float*)d_in[11];
    const float* bn_gamma = (const float*)d_in[12];
    const float* bn_beta  = (const float*)d_in[13];
    const float* bn_mean  = (const float*)d_in[14];
    const float* bn_var   = (const float*)d_in[15];
    const float* gate_w   = (const float*)d_in[16];
    const float* gate_b   = (const float*)d_in[17];
    const float* proj_w   = (const float*)d_in[18];
    const float* proj_b   = (const float*)d_in[19];
    float* out = (float*)d_out;

    cudaFuncSetAttribute(k_mmagemm, cudaFuncAttributeMaxDynamicSharedMemorySize, GEMM_SMEM);

    k_zero_cnt<<<(N_NODES + 255) / 256, 256>>>();
    k_count<<<(N_EDGES + 255) / 256, 256>>>(ei);
    k_scan<<<1, 1024>>>();
    k_scatter<<<(N_EDGES + 255) / 256, 256>>>(ei);
    k_transpose<<<dim3(32, 32, 3), dim3(32, 8)>>>(w_rest);
    k_gemm0<<<N_NODES, 256>>>(x, w0, att_src, att_dst);
    k_meanve<<<1, 256>>>(ea, w_edge, att_edge);
    k_ae_csr<<<(N_EDGES + 127) / 128, 128>>>(ea);

    for (int l = 0; l < 4; l++) {
        if (l > 0) {
            k_mmagemm<<<dim3(8, (N_NODES + 127) / 128), 256, GEMM_SMEM>>>(l, att_src, att_dst);
        }
        k_attw<<<(N_NODES + 63) / 64, 64>>>(l);
        k_agg<<<N_NODES, 128>>>(l, l < 3 ? 1 : 0, bias012, bias3,
                                bn_gamma, bn_beta, bn_mean, bn_var, gate_w, gate_b);
    }

    k_pool<<<N_GRAPH, 256>>>(batch);
    k_proj<<<N_GRAPH / 8, 256>>>(proj_w, proj_b, out);
}